// round 2
// baseline (speedup 1.0000x reference)
#include <cuda_runtime.h>
#include <cstdint>

// ---------------- problem constants ----------------
#define HW_      65536      // 256*256 dense positions
#define WGRID    256
#define CDIM     64
#define NKP      400
#define PMAX     2
#define NBLK     37         // m-chunk blocks; 37*4*2 = 296 = 2*148 SMs exactly
#define TILES_PER_BLK 14    // ceil(512/37)
#define TOTAL_M_TILES 512   // 65536/128
#define NTILES_N 4          // 4 * 100 = 400
#define N_TILE   100
#define M_TILE   128
#define TMAIN    160        // 16 tx (m) x 10 ty (n)
#define L2E      1.4426950408889634f

// ---------------- device scratch (no allocs allowed) ----------------
__device__ float g_invn[PMAX * HW_];              // 100 / ||src col||
__device__ float g_tgt [PMAX * CDIM * NKP];       // normalized tgt desc, [p][c][n]
__device__ float g_part[PMAX * NKP * NBLK * 4];   // (max, sum, cx, cy) partials

// ---------------- helpers ----------------
// Fast exp2 for x in [-inf, 0]: magic-round + degree-6 poly + exponent splice.
// ~1e-7 rel error, pure FMA/ALU (avoids MUFU throughput wall).
__device__ __forceinline__ float fexp2(float x) {
    x = fmaxf(x, -125.0f);
    float r  = x + 12582912.0f;                 // 1.5 * 2^23 magic
    int   ei = __float_as_int(r) - 0x4B400000;  // rint(x)
    float t  = r - 12582912.0f;
    float f  = x - t;                           // [-0.5, 0.5]
    float p  =            1.5403530393381609e-4f;
    p = fmaf(p, f, 1.3333558146428443e-3f);
    p = fmaf(p, f, 9.6181291076284772e-3f);
    p = fmaf(p, f, 5.5504108664821580e-2f);
    p = fmaf(p, f, 2.4022650695910071e-1f);
    p = fmaf(p, f, 6.9314718055994531e-1f);
    p = fmaf(p, f, 1.0f);
    return p * __int_as_float((ei + 127) << 23);
}

// packed f32x2 FMA (2 FMA/op; ptxas won't auto-fuse from C++)
__device__ __forceinline__ void ffma2(float2& d, unsigned long long a, unsigned long long b) {
    unsigned long long dd = *reinterpret_cast<unsigned long long*>(&d);
    asm("fma.rn.f32x2 %0, %1, %2, %0;" : "+l"(dd) : "l"(a), "l"(b));
    *reinterpret_cast<unsigned long long*>(&d) = dd;
}
__device__ __forceinline__ unsigned long long dup2(float v) {
    unsigned long long r;
    asm("mov.b64 %0, {%1, %1};" : "=l"(r) : "f"(v));
    return r;
}
__device__ __forceinline__ unsigned long long pk2(float2 v) {
    unsigned long long r;
    asm("mov.b64 %0, {%1, %2};" : "=l"(r) : "f"(v.x), "f"(v.y));
    return r;
}
__device__ __forceinline__ void cp16(float* s, const float* g) {
    unsigned saddr = (unsigned)__cvta_generic_to_shared(s);
    asm volatile("cp.async.cg.shared.global [%0], [%1], 16;\n" :: "r"(saddr), "l"(g));
}

// ---------------- kernel 1: src column inverse norms (x100 temp folded in) ----------------
__global__ void k_src_norm(const float* __restrict__ dense, const int* __restrict__ src_ids) {
    int p = blockIdx.y;
    int m = blockIdx.x * blockDim.x + threadIdx.x;
    const float* base = dense + (size_t)src_ids[p] * CDIM * HW_ + m;
    float s = 0.f;
#pragma unroll
    for (int c = 0; c < CDIM; ++c) { float v = base[(size_t)c * HW_]; s = fmaf(v, v, s); }
    float nrm = sqrtf(s);
    g_invn[p * HW_ + m] = 100.0f / fmaxf(nrm, 1e-12f);
}

// ---------------- kernel 2: normalize tgt desc, emit scores + ids ----------------
__global__ void k_tgt(const float* __restrict__ kdesc, const float* __restrict__ kscores,
                      const int* __restrict__ tgt_ids, const int* __restrict__ src_ids,
                      float* __restrict__ out, int out_size, int P) {
    int p = blockIdx.y;
    int n = blockIdx.x * blockDim.x + threadIdx.x;
    if (n < NKP) {
        const float* base = kdesc + (size_t)tgt_ids[p] * CDIM * NKP + n;
        float s = 0.f;
#pragma unroll
        for (int c = 0; c < CDIM; ++c) { float v = base[c * NKP]; s = fmaf(v, v, s); }
        float inv = 1.0f / fmaxf(sqrtf(s), 1e-12f);
#pragma unroll
        for (int c = 0; c < CDIM; ++c)
            g_tgt[((size_t)p * CDIM + c) * NKP + n] = base[c * NKP] * inv;
        // tgt_scores after coords: out[P*N*2 + p*N + n]
        int so = P * NKP * 2 + p * NKP + n;
        if (so < out_size) out[so] = kscores[tgt_ids[p] * NKP + n];
    }
    if (p == 0 && blockIdx.x == 0 && threadIdx.x == 0) {
        int base = P * NKP * 3;
        for (int pp = 0; pp < P; ++pp) {
            if (base + pp < out_size)     out[base + pp]     = (float)tgt_ids[pp];
            if (base + P + pp < out_size) out[base + P + pp] = (float)src_ids[pp];
        }
    }
}

// ---------------- kernel 3: fused GEMM + online softmax + coord accumulation ----------------
// grid (NBLK, NTILES_N, P), block 160 = 16 tx (m) x 10 ty (n)
// smem: B[2][64*128] | inv[2][128] | A[64*100]
#define SMEM_FLOATS (2*64*128 + 2*128 + 64*100)
__global__ void __launch_bounds__(TMAIN, 2)
k_match(const float* __restrict__ dense, const int* __restrict__ src_ids) {
    extern __shared__ float smem[];
    float* Bst[2]  = { smem, smem + 64 * 128 };
    float* Ist[2]  = { smem + 2 * 64 * 128, smem + 2 * 64 * 128 + 128 };
    float* As      = smem + 2 * 64 * 128 + 256;

    const int tid = threadIdx.x;
    const int tx  = tid & 15;
    const int ty  = tid >> 4;
    const int blk   = blockIdx.x;
    const int ntile = blockIdx.y;
    const int p     = blockIdx.z;

    const float* srcbase = dense + (size_t)src_ids[p] * CDIM * HW_;
    const float* invbase = g_invn + (size_t)p * HW_;

    // load normalized tgt tile: As[k*100 + nl]
    const int nbase = ntile * N_TILE;
    for (int idx = tid; idx < CDIM * N_TILE; idx += TMAIN) {
        int k = idx / N_TILE, nl = idx - k * N_TILE;
        As[idx] = g_tgt[((size_t)p * CDIM + k) * NKP + nbase + nl];
    }

    const int t0   = blk * TILES_PER_BLK;
    const int tcnt = min(TILES_PER_BLK, TOTAL_M_TILES - t0);

    float run[10], ssum[10], scx[10], scy[10];
#pragma unroll
    for (int j = 0; j < 10; ++j) { run[j] = -1e30f; ssum[j] = 0.f; scx[j] = 0.f; scy[j] = 0.f; }

    float xoffs[8];
#pragma unroll
    for (int i = 0; i < 8; ++i)
        xoffs[i] = (float)((i < 4) ? tx * 4 + i : 64 + tx * 4 + (i - 4));

    auto load_tile = [&](int t, int st) {
        int m0 = (t0 + t) * M_TILE;
        float* B = Bst[st]; float* I = Ist[st];
        for (int idx = tid; idx < 2048; idx += TMAIN) {
            int k = idx >> 5, seg = idx & 31;
            cp16(B + k * 128 + seg * 4, srcbase + (size_t)k * HW_ + m0 + seg * 4);
        }
        if (tid < 32) cp16(I + tid * 4, invbase + m0 + tid * 4);
        asm volatile("cp.async.commit_group;\n" ::);
    };

    load_tile(0, 0);

    for (int t = 0; t < tcnt; ++t) {
        const int st = t & 1;
        if (t + 1 < tcnt) {
            load_tile(t + 1, st ^ 1);
            asm volatile("cp.async.wait_group 1;\n" ::);
        } else {
            asm volatile("cp.async.wait_group 0;\n" ::);
        }
        __syncthreads();

        const float* B = Bst[st];
        const float* I = Ist[st];

        float2 acc[5][8];
#pragma unroll
        for (int j = 0; j < 5; ++j)
#pragma unroll
            for (int i = 0; i < 8; ++i) acc[j][i] = make_float2(0.f, 0.f);

#pragma unroll 4
        for (int k = 0; k < CDIM; ++k) {
            const float* brow = B + k * 128 + tx * 4;
            float4 b0 = *(const float4*)brow;
            float4 b1 = *(const float4*)(brow + 64);
            unsigned long long bd[8];
            bd[0] = dup2(b0.x); bd[1] = dup2(b0.y); bd[2] = dup2(b0.z); bd[3] = dup2(b0.w);
            bd[4] = dup2(b1.x); bd[5] = dup2(b1.y); bd[6] = dup2(b1.z); bd[7] = dup2(b1.w);
            const float* arow = As + k * N_TILE + ty * 10;
            unsigned long long ap[5];
#pragma unroll
            for (int j = 0; j < 5; ++j) ap[j] = pk2(*(const float2*)(arow + 2 * j));
#pragma unroll
            for (int j = 0; j < 5; ++j)
#pragma unroll
                for (int i = 0; i < 8; ++i) ffma2(acc[j][i], ap[j], bd[i]);
        }

        // ---- fused online-softmax epilogue for this m-tile ----
        const int m0  = (t0 + t) * M_TILE;
        const float xbf = (float)(m0 & 255);   // 0 or 128
        const float yf  = (float)(m0 >> 8);    // constant row for whole tile
        float invv[8];
#pragma unroll
        for (int i = 0; i < 8; ++i)
            invv[i] = I[(i < 4) ? tx * 4 + i : 64 + tx * 4 + (i - 4)];

#pragma unroll
        for (int j = 0; j < 5; ++j) {
#pragma unroll
            for (int c = 0; c < 2; ++c) {
                const int jj = 2 * j + c;
                float l[8];
#pragma unroll
                for (int i = 0; i < 8; ++i) {
                    float d = c ? acc[j][i].y : acc[j][i].x;
                    l[i] = d * invv[i];
                }
                float lm = fmaxf(fmaxf(fmaxf(l[0], l[1]), fmaxf(l[2], l[3])),
                                 fmaxf(fmaxf(l[4], l[5]), fmaxf(l[6], l[7])));
                float nm   = fmaxf(run[jj], lm);
                float cold = fexp2((run[jj] - nm) * L2E);
                float sw = 0.f, swx = 0.f;
#pragma unroll
                for (int i = 0; i < 8; ++i) {
                    float w = fexp2((l[i] - nm) * L2E);
                    sw  += w;
                    swx  = fmaf(w, xoffs[i], swx);
                }
                ssum[jj] = fmaf(ssum[jj], cold, sw);
                scx[jj]  = fmaf(scx[jj],  cold, fmaf(xbf, sw, swx));
                scy[jj]  = fmaf(scy[jj],  cold, yf * sw);
                run[jj]  = nm;
            }
        }
        __syncthreads();   // done reading B[st] before it is reloaded
    }

    // ---- merge across the 16 m-lanes (same ty => same n set), width-16 shuffle ----
#pragma unroll
    for (int j = 0; j < 10; ++j) {
        float m = run[j], s = ssum[j], x = scx[j], y = scy[j];
#pragma unroll
        for (int off = 1; off < 16; off <<= 1) {
            float m2 = __shfl_xor_sync(0xffffffffu, m, off, 16);
            float s2 = __shfl_xor_sync(0xffffffffu, s, off, 16);
            float x2 = __shfl_xor_sync(0xffffffffu, x, off, 16);
            float y2 = __shfl_xor_sync(0xffffffffu, y, off, 16);
            float nm = fmaxf(m, m2);
            float ca = fexp2((m  - nm) * L2E);
            float cb = fexp2((m2 - nm) * L2E);
            s = s * ca + s2 * cb;
            x = x * ca + x2 * cb;
            y = y * ca + y2 * cb;
            m = nm;
        }
        if (tx == 0) {
            int n = nbase + ty * 10 + j;
            float4 v = make_float4(m, s, x, y);
            *(float4*)&g_part[(((size_t)p * NKP + n) * NBLK + blk) * 4] = v;
        }
    }
}

// ---------------- kernel 4: combine partials -> pseudo coords ----------------
__global__ void k_combine(float* __restrict__ out, int P, int out_size) {
    int idx = blockIdx.x * blockDim.x + threadIdx.x;
    if (idx >= P * NKP) return;
    const float4* part = (const float4*)&g_part[(size_t)idx * NBLK * 4];
    float M = -1e30f;
#pragma unroll 4
    for (int b = 0; b < NBLK; ++b) M = fmaxf(M, part[b].x);
    float S = 0.f, X = 0.f, Y = 0.f;
#pragma unroll 4
    for (int b = 0; b < NBLK; ++b) {
        float4 v = part[b];
        float c = fexp2((v.x - M) * L2E);
        S = fmaf(v.y, c, S);
        X = fmaf(v.z, c, X);
        Y = fmaf(v.w, c, Y);
    }
    if (idx * 2 + 1 < out_size) {
        out[idx * 2 + 0] = X / S;
        out[idx * 2 + 1] = Y / S;
    }
}

// ---------------- launch ----------------
extern "C" void kernel_launch(void* const* d_in, const int* in_sizes, int n_in,
                              void* d_out, int out_size) {
    const float* kscores = (const float*)d_in[0];   // [BW,1,400]
    const float* kdesc   = (const float*)d_in[1];   // [BW,64,400]
    const float* dense   = (const float*)d_in[2];   // [BW,64,65536]
    const int*   tgt_ids = (const int*)d_in[3];
    const int*   src_ids = (const int*)d_in[4];
    int P = in_sizes[3];
    if (P > PMAX) P = PMAX;
    float* out = (float*)d_out;

    k_src_norm<<<dim3(HW_ / 256, P), 256>>>(dense, src_ids);
    k_tgt<<<dim3(2, P), 256>>>(kdesc, kscores, tgt_ids, src_ids, out, out_size, P);

    const int smem_bytes = SMEM_FLOATS * sizeof(float);   // ~92 KB
    cudaFuncSetAttribute(k_match, cudaFuncAttributeMaxDynamicSharedMemorySize, smem_bytes);
    k_match<<<dim3(NBLK, NTILES_N, P), TMAIN, smem_bytes>>>(dense, src_ids);

    k_combine<<<(P * NKP + 127) / 128, 128>>>(out, P, out_size);
}

// round 3
// speedup vs baseline: 1.7574x; 1.7574x over previous
#include <cuda_runtime.h>
#include <cstdint>

typedef unsigned long long ull;

// ---------------- problem constants ----------------
#define HW_      65536      // 256*256 dense positions
#define CDIM     64
#define NKP      400
#define PMAX     2
#define NBLK     37         // m-chunk blocks
#define TILES_PER_BLK 14    // ceil(512/37)
#define TOTAL_M_TILES 512   // 65536/128
#define NTILES_N 4          // 4 * 100 = 400
#define N_TILE   100
#define M_TILE   128
#define TMAIN    320        // 32 tx (m) x 10 ty (n)
#define LOGIT_C  144.26950408889634f   // 100 * log2(e)

// ---------------- device scratch ----------------
__device__ float  g_invn[PMAX * HW_];          // (100*log2e) / ||src col||
__device__ float  g_tgt [PMAX * CDIM * NKP];   // normalized tgt desc
__device__ float4 g_part4[PMAX * NKP * NBLK];  // (S, X, Y, _) partials -- plain sums

// ---------------- packed f32x2 helpers ----------------
__device__ __forceinline__ void fma2acc(ull& d, ull a, ull b) {
    asm("fma.rn.f32x2 %0, %1, %2, %0;" : "+l"(d) : "l"(a), "l"(b));
}
__device__ __forceinline__ ull fma2(ull a, ull b, ull c) {
    ull d; asm("fma.rn.f32x2 %0, %1, %2, %3;" : "=l"(d) : "l"(a), "l"(b), "l"(c)); return d;
}
__device__ __forceinline__ ull add2(ull a, ull b) {
    ull d; asm("add.rn.f32x2 %0, %1, %2;" : "=l"(d) : "l"(a), "l"(b)); return d;
}
__device__ __forceinline__ ull mul2(ull a, ull b) {
    ull d; asm("mul.rn.f32x2 %0, %1, %2;" : "=l"(d) : "l"(a), "l"(b)); return d;
}
__device__ __forceinline__ ull dup2f(float v) {
    ull r; asm("mov.b64 %0, {%1, %1};" : "=l"(r) : "f"(v)); return r;
}
__device__ __forceinline__ ull pk2f(float a, float b) {
    ull r; asm("mov.b64 %0, {%1, %2};" : "=l"(r) : "f"(a), "f"(b)); return r;
}
__device__ __forceinline__ ull pk2u(unsigned a, unsigned b) {
    ull r; asm("mov.b64 %0, {%1, %2};" : "=l"(r) : "r"(a), "r"(b)); return r;
}
__device__ __forceinline__ float2 unpk(ull a) {
    float2 v; asm("mov.b64 {%0, %1}, %2;" : "=f"(v.x), "=f"(v.y) : "l"(a)); return v;
}
__device__ __forceinline__ void cp16(float* s, const float* g) {
    unsigned saddr = (unsigned)__cvta_generic_to_shared(s);
    asm volatile("cp.async.cg.shared.global [%0], [%1], 16;\n" :: "r"(saddr), "l"(g));
}

// packed exp2 (args <= ~0, may reach -290): magic round + deg-5 poly + int splice.
// ei clamped at -126 so underflowed terms become ~1e-38 (negligible vs ~1e-18 max weight).
struct E2C { ull mag, nmag, none, c5, c4, c3, c2, c1, one; };
__device__ __forceinline__ E2C make_e2c() {
    E2C C;
    C.mag  = dup2f(12582912.0f);
    C.nmag = dup2f(-12582912.0f);
    C.none = dup2f(-1.0f);
    C.c5   = dup2f(1.3333558146428443e-3f);
    C.c4   = dup2f(9.6181291076284772e-3f);
    C.c3   = dup2f(5.5504108664821580e-2f);
    C.c2   = dup2f(2.4022650695910071e-1f);
    C.c1   = dup2f(6.9314718055994531e-1f);
    C.one  = dup2f(1.0f);
    return C;
}
__device__ __forceinline__ ull exp2p(ull x, const E2C& C) {
    ull r = add2(x, C.mag);
    ull t = add2(r, C.nmag);
    ull f = fma2(t, C.none, x);        // f = x - rint(x), in [-0.5, 0.5]
    ull p = fma2(C.c5, f, C.c4);
    p = fma2(p, f, C.c3);
    p = fma2(p, f, C.c2);
    p = fma2(p, f, C.c1);
    p = fma2(p, f, C.one);
    unsigned lo = (unsigned)r, hi = (unsigned)(r >> 32);
    lo = (unsigned)max((int)lo, (int)0x4B3FFF82);   // clamp ei >= -126
    hi = (unsigned)max((int)hi, (int)0x4B3FFF82);
    lo = (lo + 0xB4C0007Fu) << 23;                  // ((ei+127)<<23)
    hi = (hi + 0xB4C0007Fu) << 23;
    return mul2(p, pk2u(lo, hi));
}

// ---------------- kernel 1: src column inverse norms (temp*log2e folded) ----------------
__global__ void k_src_norm(const float* __restrict__ dense, const int* __restrict__ src_ids) {
    int p = blockIdx.y;
    int m = blockIdx.x * blockDim.x + threadIdx.x;
    const float* base = dense + (size_t)src_ids[p] * CDIM * HW_ + m;
    float s = 0.f;
#pragma unroll
    for (int c = 0; c < CDIM; ++c) { float v = base[(size_t)c * HW_]; s = fmaf(v, v, s); }
    g_invn[p * HW_ + m] = LOGIT_C / fmaxf(sqrtf(s), 1e-12f);
}

// ---------------- kernel 2: normalize tgt desc, emit scores + ids ----------------
__global__ void k_tgt(const float* __restrict__ kdesc, const float* __restrict__ kscores,
                      const int* __restrict__ tgt_ids, const int* __restrict__ src_ids,
                      float* __restrict__ out, int out_size, int P) {
    int p = blockIdx.y;
    int n = blockIdx.x * blockDim.x + threadIdx.x;
    if (n < NKP) {
        const float* base = kdesc + (size_t)tgt_ids[p] * CDIM * NKP + n;
        float s = 0.f;
#pragma unroll
        for (int c = 0; c < CDIM; ++c) { float v = base[c * NKP]; s = fmaf(v, v, s); }
        float inv = 1.0f / fmaxf(sqrtf(s), 1e-12f);
#pragma unroll
        for (int c = 0; c < CDIM; ++c)
            g_tgt[((size_t)p * CDIM + c) * NKP + n] = base[c * NKP] * inv;
        int so = P * NKP * 2 + p * NKP + n;
        if (so < out_size) out[so] = kscores[tgt_ids[p] * NKP + n];
    }
    if (p == 0 && blockIdx.x == 0 && threadIdx.x == 0) {
        int base = P * NKP * 3;
        for (int pp = 0; pp < P; ++pp) {
            if (base + pp < out_size)     out[base + pp]     = (float)tgt_ids[pp];
            if (base + P + pp < out_size) out[base + P + pp] = (float)src_ids[pp];
        }
    }
}

// ---------------- kernel 3: GEMM + fixed-shift softmax accumulation ----------------
// grid (NBLK, NTILES_N, P), block 320 = 32 tx (m, 4 each) x 10 ty (n, 10 each)
// smem: B[2][64*128] | inv[2][128] | A2dup[64*200]
#define SMEM_FLOATS (2*64*128 + 2*128 + 64*200)
__global__ void __launch_bounds__(TMAIN, 1)
k_match(const float* __restrict__ dense, const int* __restrict__ src_ids) {
    extern __shared__ float smem[];
    float* B0  = smem;                     // 2 x 8192
    float* I0  = smem + 2 * 64 * 128;      // 2 x 128
    float* As2 = smem + 2 * 64 * 128 + 256; // 64 x 200 (A duplicated pairs)

    const int tid = threadIdx.x;
    const int tx  = tid & 31;
    const int ty  = tid >> 5;
    const int blk = blockIdx.x, ntile = blockIdx.y, p = blockIdx.z;

    const float* srcbase = dense + (size_t)src_ids[p] * CDIM * HW_;
    const float* invbase = g_invn + (size_t)p * HW_;
    const int nbase = ntile * N_TILE;

    // build duplicated A tile: As2[k][2n] = As2[k][2n+1] = that(k,n)
    for (int idx = tid; idx < CDIM * N_TILE; idx += TMAIN) {
        int k = idx / N_TILE, nl = idx - k * N_TILE;
        float v = g_tgt[((size_t)p * CDIM + k) * NKP + nbase + nl];
        As2[k * 200 + 2 * nl]     = v;
        As2[k * 200 + 2 * nl + 1] = v;
    }

    const int t0   = blk * TILES_PER_BLK;
    const int tcnt = min(TILES_PER_BLK, TOTAL_M_TILES - t0);

    ull S2[10], X2[10], Y2[10];
#pragma unroll
    for (int j = 0; j < 10; ++j) { S2[j] = 0ULL; X2[j] = 0ULL; Y2[j] = 0ULL; }

    const E2C C  = make_e2c();
    const ull CN = dup2f(-LOGIT_C);

    auto load_tile = [&](int t, int st) {
        int m0 = (t0 + t) * M_TILE;
        float* B = B0 + st * 8192;
        float* I = I0 + st * 128;
        for (int idx = tid; idx < 2048; idx += TMAIN) {
            int k = idx >> 5, seg = idx & 31;
            cp16(B + k * 128 + seg * 4, srcbase + (size_t)k * HW_ + m0 + seg * 4);
        }
        if (tid < 32) cp16(I + tid * 4, invbase + m0 + tid * 4);
        asm volatile("cp.async.commit_group;\n" ::);
    };

    load_tile(0, 0);

    for (int t = 0; t < tcnt; ++t) {
        const int st = t & 1;
        if (t + 1 < tcnt) {
            load_tile(t + 1, st ^ 1);
            asm volatile("cp.async.wait_group 1;\n" ::);
        } else {
            asm volatile("cp.async.wait_group 0;\n" ::);
        }
        __syncthreads();

        const float* B = B0 + st * 8192;
        ull acc[10][2];
#pragma unroll
        for (int j = 0; j < 10; ++j) { acc[j][0] = 0ULL; acc[j][1] = 0ULL; }

        const float* arow0 = As2 + ty * 20;
#pragma unroll 4
        for (int k = 0; k < CDIM; ++k) {
            ulonglong2 b = *(const ulonglong2*)(B + k * 128 + tx * 4);  // 4 m vals as 2 pairs
            const float* ar = arow0 + k * 200;
#pragma unroll
            for (int jp = 0; jp < 5; ++jp) {
                ulonglong2 av = *(const ulonglong2*)(ar + 4 * jp);      // (a,a),(a',a')
                fma2acc(acc[2 * jp][0],     av.x, b.x);
                fma2acc(acc[2 * jp][1],     av.x, b.y);
                fma2acc(acc[2 * jp + 1][0], av.y, b.x);
                fma2acc(acc[2 * jp + 1][1], av.y, b.y);
            }
        }

        // ---- packed epilogue: w = exp2(acc*inv - 100*log2e), accumulate S/X/Y ----
        const float* I = I0 + st * 128;
        ulonglong2 iv = *(const ulonglong2*)(I + tx * 4);   // inv-norm pairs over m
        const int m0v = (t0 + t) * M_TILE;
        const float xb = (float)(m0v & 255);
        const ull yf2 = dup2f((float)(m0v >> 8));
        const ull xo0 = pk2f(xb + (float)(tx * 4 + 0), xb + (float)(tx * 4 + 1));
        const ull xo1 = pk2f(xb + (float)(tx * 4 + 2), xb + (float)(tx * 4 + 3));

#pragma unroll
        for (int j = 0; j < 10; ++j) {
            ull w0 = exp2p(fma2(acc[j][0], iv.x, CN), C);
            ull w1 = exp2p(fma2(acc[j][1], iv.y, CN), C);
            ull stile = add2(w0, w1);
            S2[j] = add2(S2[j], stile);
            Y2[j] = fma2(stile, yf2, Y2[j]);
            X2[j] = fma2(w0, xo0, X2[j]);
            X2[j] = fma2(w1, xo1, X2[j]);
        }
        __syncthreads();
    }

    // ---- reduce across the 32 m-lanes (warp == one ty) : plain sums ----
#pragma unroll
    for (int j = 0; j < 10; ++j) {
        float2 sv = unpk(S2[j]); float s = sv.x + sv.y;
        float2 xv = unpk(X2[j]); float x = xv.x + xv.y;
        float2 yv = unpk(Y2[j]); float y = yv.x + yv.y;
#pragma unroll
        for (int off = 16; off; off >>= 1) {
            s += __shfl_xor_sync(0xffffffffu, s, off);
            x += __shfl_xor_sync(0xffffffffu, x, off);
            y += __shfl_xor_sync(0xffffffffu, y, off);
        }
        if (tx == 0)
            g_part4[((size_t)p * NKP + nbase + ty * 10 + j) * NBLK + blk] =
                make_float4(s, x, y, 0.f);
    }
}

// ---------------- kernel 4: combine partials (one warp per keypoint) ----------------
__global__ void k_combine(float* __restrict__ out, int P, int out_size) {
    int gw   = (blockIdx.x * blockDim.x + threadIdx.x) >> 5;
    int lane = threadIdx.x & 31;
    if (gw >= P * NKP) return;
    float S = 0.f, X = 0.f, Y = 0.f;
    for (int b = lane; b < NBLK; b += 32) {
        float4 v = g_part4[(size_t)gw * NBLK + b];
        S += v.x; X += v.y; Y += v.z;
    }
#pragma unroll
    for (int off = 16; off; off >>= 1) {
        S += __shfl_xor_sync(0xffffffffu, S, off);
        X += __shfl_xor_sync(0xffffffffu, X, off);
        Y += __shfl_xor_sync(0xffffffffu, Y, off);
    }
    if (lane == 0 && gw * 2 + 1 < out_size) {
        out[gw * 2 + 0] = X / S;
        out[gw * 2 + 1] = Y / S;
    }
}

// ---------------- launch ----------------
extern "C" void kernel_launch(void* const* d_in, const int* in_sizes, int n_in,
                              void* d_out, int out_size) {
    const float* kscores = (const float*)d_in[0];
    const float* kdesc   = (const float*)d_in[1];
    const float* dense   = (const float*)d_in[2];
    const int*   tgt_ids = (const int*)d_in[3];
    const int*   src_ids = (const int*)d_in[4];
    int P = in_sizes[3];
    if (P > PMAX) P = PMAX;
    float* out = (float*)d_out;

    k_src_norm<<<dim3(HW_ / 256, P), 256>>>(dense, src_ids);
    k_tgt<<<dim3(2, P), 256>>>(kdesc, kscores, tgt_ids, src_ids, out, out_size, P);

    const int smem_bytes = SMEM_FLOATS * sizeof(float);   // 117,760 B
    cudaFuncSetAttribute(k_match, cudaFuncAttributeMaxDynamicSharedMemorySize, smem_bytes);
    k_match<<<dim3(NBLK, NTILES_N, P), TMAIN, smem_bytes>>>(dense, src_ids);

    k_combine<<<(P * NKP * 32 + 255) / 256, 256>>>(out, P, out_size);
}